// round 3
// baseline (speedup 1.0000x reference)
#include <cuda_runtime.h>
#include <math.h>

// Problem constants
#define BATCH 4
#define CCH   64
#define HH    256
#define WW    256
#define HW    (HH*WW)
#define CMID  16
#define CIN   73
#define EPSV  1e-8f

// Tiling
#define TS    16            // output tile side
#define HALO  18            // TS + 2
#define NHP   (HALO*HALO)   // 324 halo pixels
#define PPX   68            // padded floats per pixel in smem x-tile (bank-friendly)
#define PPX4  17            // PPX/4

// Scratch (device globals — no allocation inside kernel_launch)
__device__ float g_xT [BATCH*HW*CCH];   // NHWC x, 67MB
__device__ float g_sim[BATCH*HW*9];     // similarity, 9.4MB
__device__ float g_hm [BATCH*HW*CMID];  // mid features NHWC16, 16.8MB

// ---------------------------------------------------------------------------
// K1: NCHW -> NHWC transpose (per batch: 64 x 65536 matrix transpose)
// ---------------------------------------------------------------------------
__global__ __launch_bounds__(256) void k_transpose(const float* __restrict__ x) {
    __shared__ float s[64][65];
    int blk = blockIdx.x;            // 4096 blocks
    int b   = blk >> 10;
    int p0  = (blk & 1023) << 6;     // 64 pixels per block
    int tid = threadIdx.x;
    const float* xb = x + b*CCH*HW;

    int pl = tid & 63;
    int c0 = tid >> 6;               // 0..3
#pragma unroll
    for (int i = 0; i < 16; i++) {
        int c = c0 + i*4;
        s[c][pl] = xb[c*HW + p0 + pl];
    }
    __syncthreads();

    int c4 = tid & 15;               // float4 slot within pixel
    int pq = tid >> 4;               // 0..15
    float* out = g_xT + b*HW*CCH;
#pragma unroll
    for (int j = 0; j < 4; j++) {
        int p = pq + j*16;
        float4 v = make_float4(s[c4*4+0][p], s[c4*4+1][p], s[c4*4+2][p], s[c4*4+3][p]);
        reinterpret_cast<float4*>(out + (p0+p)*CCH)[c4] = v;
    }
}

// ---------------------------------------------------------------------------
// K2: local cosine similarity (9 neighbors), zero-padded borders
// ---------------------------------------------------------------------------
__global__ __launch_bounds__(256, 2) void k_sim() {
    extern __shared__ float sm2[];
    float* tile = sm2;               // NHP * PPX
    float* rn   = sm2 + NHP*PPX;     // NHP reciprocal (norm+eps)

    int blk = blockIdx.x;            // 1024 blocks
    int b   = blk >> 8;
    int tt  = blk & 255;
    int by  = (tt >> 4) * TS, bx = (tt & 15) * TS;
    int tid = threadIdx.x;
    const float* xb = g_xT + b*HW*CCH;

    // load halo tile (float4, zero OOB)
    for (int idx = tid; idx < NHP*16; idx += 256) {
        int hp = idx >> 4, c4 = idx & 15;
        int hy = by + hp/HALO - 1, hx = bx + hp%HALO - 1;
        float4 v = make_float4(0.f, 0.f, 0.f, 0.f);
        if ((unsigned)hy < HH && (unsigned)hx < WW)
            v = reinterpret_cast<const float4*>(xb + (hy*WW + hx)*CCH)[c4];
        reinterpret_cast<float4*>(tile + hp*PPX)[c4] = v;
    }
    __syncthreads();

    // per-halo-pixel reciprocal norms
    for (int i = tid; i < NHP; i += 256) {
        const float4* tp = reinterpret_cast<const float4*>(tile + i*PPX);
        float ssum = 0.f;
#pragma unroll
        for (int c4 = 0; c4 < 16; c4++) {
            float4 v = tp[c4];
            ssum += v.x*v.x + v.y*v.y + v.z*v.z + v.w*v.w;
        }
        rn[i] = 1.0f / (sqrtf(ssum) + EPSV);
    }
    __syncthreads();

    int ty = tid >> 4, tx = tid & 15;
    int hc = (ty+1)*HALO + (tx+1);
    const float4* tp = reinterpret_cast<const float4*>(tile);

    float acc[9];
#pragma unroll
    for (int k = 0; k < 9; k++) acc[k] = 0.f;

#pragma unroll 4
    for (int c4 = 0; c4 < 16; c4++) {
        float4 cen = tp[hc*PPX4 + c4];
#pragma unroll
        for (int dy = 0; dy < 3; dy++)
#pragma unroll
        for (int dx = 0; dx < 3; dx++) {
            int nb = hc + (dy-1)*HALO + (dx-1);
            float4 v = tp[nb*PPX4 + c4];
            acc[dy*3+dx] += cen.x*v.x + cen.y*v.y + cen.z*v.z + cen.w*v.w;
        }
    }
    float rc = rn[hc];
    float* so = g_sim + (b*HW + (by+ty)*WW + (bx+tx))*9;
#pragma unroll
    for (int dy = 0; dy < 3; dy++)
#pragma unroll
    for (int dx = 0; dx < 3; dx++) {
        int nb = hc + (dy-1)*HALO + (dx-1);
        so[dy*3+dx] = acc[dy*3+dx] * rc * rn[nb];
    }
}

// ---------------------------------------------------------------------------
// K3: conv1 (73 -> 16, 3x3, pad 1) + leaky relu.  FMA-pipe-bound design:
// thread = 4 pixels x 4 out-channels (16 accumulators), weights in smem.
// ---------------------------------------------------------------------------
__global__ __launch_bounds__(256, 1) void k_conv1(const float* __restrict__ w1,
                                                  const float* __restrict__ b1) {
    extern __shared__ float sm3[];
    float* xt   = sm3;                    // NHP*PPX       (22032)
    float* st   = xt  + NHP*PPX;          // NHP*9         ( 2916)
    float* wsx  = st  + NHP*9;            // 9*16*16*4     ( 9216)
    float* wss  = wsx + 9216;             // 9*9*16        ( 1296)
    float* b1s  = wss + 1296;             // 16

    int blk = blockIdx.x;
    int b   = blk >> 8;
    int tt  = blk & 255;
    int by  = (tt >> 4) * TS, bx = (tt & 15) * TS;
    int tid = threadIdx.x;
    const float* xb = g_xT + b*HW*CCH;
    const float* sb = g_sim + b*HW*9;

    // x halo
    for (int idx = tid; idx < NHP*16; idx += 256) {
        int hp = idx >> 4, c4 = idx & 15;
        int hy = by + hp/HALO - 1, hx = bx + hp%HALO - 1;
        float4 v = make_float4(0.f, 0.f, 0.f, 0.f);
        if ((unsigned)hy < HH && (unsigned)hx < WW)
            v = reinterpret_cast<const float4*>(xb + (hy*WW + hx)*CCH)[c4];
        reinterpret_cast<float4*>(xt + hp*PPX)[c4] = v;
    }
    // sim halo
    for (int idx = tid; idx < NHP*9; idx += 256) {
        int hp = idx / 9, k = idx - hp*9;
        int hy = by + hp/HALO - 1, hx = bx + hp%HALO - 1;
        float v = 0.f;
        if ((unsigned)hy < HH && (unsigned)hx < WW)
            v = sb[(hy*WW + hx)*9 + k];
        st[hp*9 + k] = v;
    }
    // weights, x part: wsx[((t*16+c4)*16 + o)*4 + j] = w1[o][c4*4+j][r][s]
    for (int i = tid; i < 9216; i += 256) {
        int tp = i >> 10;
        int c4 = (i >> 6) & 15;
        int o  = (i >> 2) & 15;
        int j  = i & 3;
        int ci = c4*4 + j;
        int r  = tp / 3, s = tp - r*3;
        wsx[i] = w1[((o*CIN + ci)*3 + r)*3 + s];
    }
    // weights, sim part: wss[(t*9+k)*16 + o] = w1[o][64+k][r][s]
    for (int i = tid; i < 1296; i += 256) {
        int tp  = i / 144;
        int rem = i - tp*144;
        int k   = rem >> 4;
        int o   = rem & 15;
        int r   = tp / 3, s = tp - r*3;
        wss[i] = w1[((o*CIN + 64 + k)*3 + r)*3 + s];
    }
    if (tid < 16) b1s[tid] = b1[tid];
    __syncthreads();

    int og  = tid & 3;                 // out-channel group (4 ch)
    int pg  = tid >> 2;                // pixel group (4 px, same row)
    int p0  = pg * 4;
    int py  = p0 >> 4, px0 = p0 & 15;

    float acc[4][4];
#pragma unroll
    for (int i = 0; i < 4; i++)
#pragma unroll
        for (int j = 0; j < 4; j++) acc[i][j] = b1s[og*4 + j];

    const float4* xt4  = reinterpret_cast<const float4*>(xt);
    const float4* wsx4 = reinterpret_cast<const float4*>(wsx);

#pragma unroll 1
    for (int tp = 0; tp < 9; tp++) {
        int r = tp / 3, s = tp - r*3;
        int hb = (py + r)*HALO + (px0 + s);
        const float4* xrow  = xt4  + hb*PPX4;
        const float4* wrow  = wsx4 + tp*256 + og*4;
        const float*  srow  = st   + hb*9;
        const float*  wsrow = wss  + tp*144 + og*4;

#pragma unroll 4
        for (int c4 = 0; c4 < 16; c4++) {
            float4 f[4], wv[4];
#pragma unroll
            for (int i = 0; i < 4; i++) f[i]  = xrow[i*PPX4 + c4];
#pragma unroll
            for (int j = 0; j < 4; j++) wv[j] = wrow[c4*16 + j];
#pragma unroll
            for (int i = 0; i < 4; i++)
#pragma unroll
                for (int j = 0; j < 4; j++)
                    acc[i][j] += f[i].x*wv[j].x + f[i].y*wv[j].y
                               + f[i].z*wv[j].z + f[i].w*wv[j].w;
        }
#pragma unroll 3
        for (int k = 0; k < 9; k++) {
            float fs[4], wq[4];
#pragma unroll
            for (int i = 0; i < 4; i++) fs[i] = srow[i*9 + k];
#pragma unroll
            for (int j = 0; j < 4; j++) wq[j] = wsrow[k*16 + j];
#pragma unroll
            for (int i = 0; i < 4; i++)
#pragma unroll
                for (int j = 0; j < 4; j++)
                    acc[i][j] += fs[i]*wq[j];
        }
    }

    int pbase = b*HW + (by + py)*WW + bx + px0;
#pragma unroll
    for (int i = 0; i < 4; i++) {
        float4 v;
        v.x = acc[i][0] >= 0.f ? acc[i][0] : 0.2f*acc[i][0];
        v.y = acc[i][1] >= 0.f ? acc[i][1] : 0.2f*acc[i][1];
        v.z = acc[i][2] >= 0.f ? acc[i][2] : 0.2f*acc[i][2];
        v.w = acc[i][3] >= 0.f ? acc[i][3] : 0.2f*acc[i][3];
        reinterpret_cast<float4*>(g_hm + (pbase + i)*CMID)[og] = v;
    }
}

// ---------------------------------------------------------------------------
// K4: conv2 (16 -> 2, 3x3) + tanh*0.1 offset + bilinear border grid-sample
// ---------------------------------------------------------------------------
__global__ __launch_bounds__(256) void k_sample(const float* __restrict__ w2,
                                                const float* __restrict__ b2,
                                                float* __restrict__ out) {
    __shared__ float ht[NHP*17];      // stride 17 -> conflict-free scalar LDS
    __shared__ float ws2[288];
    __shared__ float b2s[2];

    int blk = blockIdx.x;
    int b   = blk >> 8;
    int tt  = blk & 255;
    int by  = (tt >> 4) * TS, bx = (tt & 15) * TS;
    int tid = threadIdx.x;
    const float* hb = g_hm + b*HW*CMID;

    for (int idx = tid; idx < NHP*16; idx += 256) {
        int hp = idx >> 4, c = idx & 15;
        int hy = by + hp/HALO - 1, hx = bx + hp%HALO - 1;
        float v = 0.f;
        if ((unsigned)hy < HH && (unsigned)hx < WW)
            v = hb[(hy*WW + hx)*CMID + c];
        ht[hp*17 + c] = v;
    }
    // ws2[(t*16+c)*2 + o] = w2[o][c][r][s]
    for (int i = tid; i < 288; i += 256) {
        int tp = i >> 5, c = (i >> 1) & 15, o = i & 1;
        int r  = tp / 3, s = tp - r*3;
        ws2[i] = w2[((o*CMID + c)*3 + r)*3 + s];
    }
    if (tid < 2) b2s[tid] = b2[tid];
    __syncthreads();

    int ty = tid >> 4, tx = tid & 15;
    float a0 = b2s[0], a1 = b2s[1];
#pragma unroll
    for (int tp = 0; tp < 9; tp++) {
        int r = tp / 3, s = tp - r*3;
        const float* row = ht + ((ty + r)*HALO + (tx + s))*17;
        const float* wr  = ws2 + tp*32;
#pragma unroll
        for (int c = 0; c < 16; c++) {
            float f = row[c];
            a0 += f * wr[c*2];
            a1 += f * wr[c*2 + 1];
        }
    }
    float offx = tanhf(a0) * 0.1f;
    float offy = tanhf(a1) * 0.1f;

    int gx = bx + tx, gy = by + ty;
    float ix = (float)gx + offx * 127.5f;   // (grid_x+1)*0.5*(W-1) with grid_x=-1+2w/255
    float iy = (float)gy + offy * 127.5f;
    ix = fminf(fmaxf(ix, 0.f), 255.f);
    iy = fminf(fmaxf(iy, 0.f), 255.f);
    float x0f = floorf(ix), y0f = floorf(iy);
    float wx = ix - x0f,  wy = iy - y0f;
    int x0 = (int)x0f, y0 = (int)y0f;
    int x1 = min(x0 + 1, WW - 1), y1 = min(y0 + 1, HH - 1);

    const float4* xb4 = reinterpret_cast<const float4*>(g_xT + b*HW*CCH);
    int p00 = (y0*WW + x0)*16, p01 = (y0*WW + x1)*16;
    int p10 = (y1*WW + x0)*16, p11 = (y1*WW + x1)*16;

    float* ob = out + b*CCH*HW + gy*WW + gx;
    float omwx = 1.f - wx, omwy = 1.f - wy;
#pragma unroll
    for (int c4 = 0; c4 < 16; c4++) {
        float4 v00 = xb4[p00 + c4], v01 = xb4[p01 + c4];
        float4 v10 = xb4[p10 + c4], v11 = xb4[p11 + c4];
        float tx0 = omwx*v00.x + wx*v01.x, bx0 = omwx*v10.x + wx*v11.x;
        float tx1 = omwx*v00.y + wx*v01.y, bx1 = omwx*v10.y + wx*v11.y;
        float tx2 = omwx*v00.z + wx*v01.z, bx2 = omwx*v10.z + wx*v11.z;
        float tx3 = omwx*v00.w + wx*v01.w, bx3 = omwx*v10.w + wx*v11.w;
        ob[(c4*4 + 0)*HW] = omwy*tx0 + wy*bx0;
        ob[(c4*4 + 1)*HW] = omwy*tx1 + wy*bx1;
        ob[(c4*4 + 2)*HW] = omwy*tx2 + wy*bx2;
        ob[(c4*4 + 3)*HW] = omwy*tx3 + wy*bx3;
    }
}

// ---------------------------------------------------------------------------
extern "C" void kernel_launch(void* const* d_in, const int* in_sizes, int n_in,
                              void* d_out, int out_size) {
    const float* x  = (const float*)d_in[0];
    const float* w1 = (const float*)d_in[1];
    const float* b1 = (const float*)d_in[2];
    const float* w2 = (const float*)d_in[3];
    const float* b2 = (const float*)d_in[4];
    float* out = (float*)d_out;

    const int smem2 = (NHP*PPX + NHP) * 4;                          // 89,424 B
    const int smem3 = (NHP*PPX + NHP*9 + 9216 + 1296 + 16) * 4;     // 141,904 B
    cudaFuncSetAttribute(k_sim,   cudaFuncAttributeMaxDynamicSharedMemorySize, smem2);
    cudaFuncSetAttribute(k_conv1, cudaFuncAttributeMaxDynamicSharedMemorySize, smem3);

    k_transpose<<<BATCH * (HW/64), 256>>>(x);
    k_sim      <<<BATCH * 256, 256, smem2>>>();
    k_conv1    <<<BATCH * 256, 256, smem3>>>(w1, b1);
    k_sample   <<<BATCH * 256, 256>>>(w2, b2, out);
    (void)in_sizes; (void)n_in; (void)out_size;
}

// round 4
// speedup vs baseline: 1.3320x; 1.3320x over previous
#include <cuda_runtime.h>
#include <math.h>

typedef unsigned long long ull;

#define BATCH 4
#define CCH   64
#define HH    256
#define WW    256
#define HW    65536
#define CMID  16
#define CIN   73
#define EPSV  1e-8f

#define TS    16
#define H18   18
#define H20   20
#define N18   324
#define N20   400
#define PPX   68
#define PPX4  17

// Scratch (device globals — no allocation inside kernel_launch)
__device__ float g_xT[BATCH*HW*CCH];    // NHWC x
__device__ float g_hm[BATCH*HW*CMID];   // mid features NHWC16

// ---- packed f32x2 helpers (FFMA2 path) ----
__device__ __forceinline__ void fma2(ull &d, ull a, ull b) {
    asm("fma.rn.f32x2 %0, %1, %2, %0;" : "+l"(d) : "l"(a), "l"(b));
}
__device__ __forceinline__ ull pk2(float lo, float hi) {
    ull r; asm("mov.b64 %0, {%1, %2};" : "=l"(r) : "f"(lo), "f"(hi)); return r;
}
__device__ __forceinline__ float red2(ull v) {
    float lo, hi; asm("mov.b64 {%0, %1}, %2;" : "=f"(lo), "=f"(hi) : "l"(v));
    return lo + hi;
}

// ---------------------------------------------------------------------------
// K1: NCHW -> NHWC transpose
// ---------------------------------------------------------------------------
__global__ __launch_bounds__(256) void k_transpose(const float* __restrict__ x) {
    __shared__ float s[64][65];
    int blk = blockIdx.x;
    int b   = blk >> 10;
    int p0  = (blk & 1023) << 6;
    int tid = threadIdx.x;
    const float* xb = x + b*CCH*HW;

    int pl = tid & 63;
    int c0 = tid >> 6;
#pragma unroll
    for (int i = 0; i < 16; i++) {
        int c = c0 + i*4;
        s[c][pl] = xb[c*HW + p0 + pl];
    }
    __syncthreads();

    int c4 = tid & 15;
    int pq = tid >> 4;
    float* out = g_xT + b*HW*CCH;
#pragma unroll
    for (int j = 0; j < 4; j++) {
        int p = pq + j*16;
        float4 v = make_float4(s[c4*4+0][p], s[c4*4+1][p], s[c4*4+2][p], s[c4*4+3][p]);
        reinterpret_cast<float4*>(out + (p0+p)*CCH)[c4] = v;
    }
}

// ---------------------------------------------------------------------------
// K2: fused cosine-sim + conv1 (73->16, 3x3, pad 1) + leaky relu, FFMA2 math
// ---------------------------------------------------------------------------
__global__ __launch_bounds__(256, 1) void k_conv1(const float* __restrict__ w1,
                                                  const float* __restrict__ b1) {
    extern __shared__ float sm[];
    float* xt  = sm;              // N20*PPX = 27200 floats (20x20 x-halo)
    float* rn  = sm + 27200;      // 400
    float* st  = sm + 27600;      // 324*10 = 3240 (sim halo, stride 10, slot 9 zeroed)
    float* wsx = sm + 30840;      // 9*16*16*4 = 9216
    float* wss = sm + 40056;      // 9*16*10  = 1440
    float* b1s = sm + 41496;      // 16        -> total 41512 floats = 166048 B

    int blk = blockIdx.x;
    int b   = blk >> 8;
    int tt  = blk & 255;
    int by  = (tt >> 4) * TS, bx = (tt & 15) * TS;
    int tid = threadIdx.x;
    const float* xb = g_xT + b*HW*CCH;

    // A: load 20x20 x halo (zero OOB)
    for (int idx = tid; idx < N20*16; idx += 256) {
        int hp = idx >> 4, c4 = idx & 15;
        int hy = by + hp/H20 - 2, hx = bx + hp%H20 - 2;
        float4 v = make_float4(0.f, 0.f, 0.f, 0.f);
        if ((unsigned)hy < HH && (unsigned)hx < WW)
            v = reinterpret_cast<const float4*>(xb + (hy*WW + hx)*CCH)[c4];
        reinterpret_cast<float4*>(xt + hp*PPX)[c4] = v;
    }
    // weights (independent of xt; before the sync)
    for (int i = tid; i < 9216; i += 256) {
        int tp   = i >> 10;
        int c4   = (i >> 6) & 15;
        int slot = (i >> 2) & 15;          // slot = j*4 + og
        int comp = i & 3;
        int o  = (slot & 3) * 4 + (slot >> 2);
        int ci = c4*4 + comp;
        int r  = tp / 3, s5 = tp - r*3;
        wsx[i] = w1[((o*CIN + ci)*3 + r)*3 + s5];
    }
    for (int i = tid; i < 1440; i += 256) {
        int tp  = i / 160;
        int rem = i - tp*160;
        int o   = rem / 10;
        int k   = rem - o*10;
        int r   = tp / 3, s5 = tp - r*3;
        wss[i] = (k < 9) ? w1[((o*CIN + 64 + k)*3 + r)*3 + s5] : 0.f;
    }
    if (tid < 16) b1s[tid] = b1[tid];
    __syncthreads();

    // B: reciprocal norms for all 400 halo2 pixels
    for (int i = tid; i < N20; i += 256) {
        const float4* tp4 = reinterpret_cast<const float4*>(xt + i*PPX);
        float ssum = 0.f;
#pragma unroll
        for (int c4 = 0; c4 < 16; c4++) {
            float4 v = tp4[c4];
            ssum += v.x*v.x + v.y*v.y + v.z*v.z + v.w*v.w;
        }
        rn[i] = 1.0f / (sqrtf(ssum) + EPSV);
    }
    __syncthreads();

    // C: cosine similarity for the 18x18 conv halo
    const ulonglong2* xt2 = reinterpret_cast<const ulonglong2*>(xt);
    for (int hp = tid; hp < N18; hp += 256) {
        int hy = hp / H18, hx = hp - hy*H18;
        int c20 = (hy+1)*H20 + (hx+1);
        ull acc[9];
#pragma unroll
        for (int k = 0; k < 9; k++) acc[k] = 0ULL;
#pragma unroll 4
        for (int c4 = 0; c4 < 16; c4++) {
            ulonglong2 cen = xt2[c20*PPX4 + c4];
#pragma unroll
            for (int dy = 0; dy < 3; dy++)
#pragma unroll
            for (int dx = 0; dx < 3; dx++) {
                ulonglong2 nb = xt2[(c20 + (dy-1)*H20 + (dx-1))*PPX4 + c4];
                fma2(acc[dy*3+dx], cen.x, nb.x);
                fma2(acc[dy*3+dx], cen.y, nb.y);
            }
        }
        float rc = rn[c20];
#pragma unroll
        for (int dy = 0; dy < 3; dy++)
#pragma unroll
        for (int dx = 0; dx < 3; dx++)
            st[hp*10 + dy*3+dx] = red2(acc[dy*3+dx]) * rc * rn[c20 + (dy-1)*H20 + (dx-1)];
        st[hp*10 + 9] = 0.f;
    }
    __syncthreads();

    // E: main conv. thread = 4 pixels (row-stride 4) x 4 out-channels.
    int og  = tid & 3;
    int pg  = tid >> 2;           // 0..63
    int py0 = pg >> 4;            // 0..3  (rows py0, py0+4, py0+8, py0+12)
    int px  = pg & 15;

    ull acc2[4][4];
#pragma unroll
    for (int i = 0; i < 4; i++)
#pragma unroll
        for (int j = 0; j < 4; j++) acc2[i][j] = pk2(b1s[og*4 + j], 0.f);

    const ulonglong2* wsx2 = reinterpret_cast<const ulonglong2*>(wsx);

#pragma unroll 1
    for (int tp = 0; tp < 9; tp++) {
        int r = tp / 3, s5 = tp - r*3;
        int hb20 = (py0 + r + 1)*H20 + (px + s5 + 1);
        int hb18 = (py0 + r)*H18 + (px + s5);
        const ulonglong2* wt = wsx2 + tp*256 + og;

#pragma unroll 4
        for (int c4 = 0; c4 < 16; c4++) {
            ulonglong2 f[4];
#pragma unroll
            for (int i = 0; i < 4; i++) f[i] = xt2[(hb20 + i*4*H20)*PPX4 + c4];
            ulonglong2 wv[4];
#pragma unroll
            for (int j = 0; j < 4; j++) wv[j] = wt[c4*16 + j*4];
#pragma unroll
            for (int i = 0; i < 4; i++)
#pragma unroll
                for (int j = 0; j < 4; j++) {
                    fma2(acc2[i][j], f[i].x, wv[j].x);
                    fma2(acc2[i][j], f[i].y, wv[j].y);
                }
        }
        // sim-feature part (9 channels, packed in k-pairs; pad slot is zero)
        const float* wro = wss + tp*160 + og*40;
#pragma unroll
        for (int kk = 0; kk < 5; kk++) {
            ull wv2[4];
#pragma unroll
            for (int j = 0; j < 4; j++)
                wv2[j] = *reinterpret_cast<const ull*>(wro + j*10 + 2*kk);
#pragma unroll
            for (int i = 0; i < 4; i++) {
                ull fv = *reinterpret_cast<const ull*>(st + (hb18 + i*4*H18)*10 + 2*kk);
#pragma unroll
                for (int j = 0; j < 4; j++) fma2(acc2[i][j], fv, wv2[j]);
            }
        }
    }

#pragma unroll
    for (int i = 0; i < 4; i++) {
        float a0 = red2(acc2[i][0]); a0 = a0 >= 0.f ? a0 : 0.2f*a0;
        float a1 = red2(acc2[i][1]); a1 = a1 >= 0.f ? a1 : 0.2f*a1;
        float a2 = red2(acc2[i][2]); a2 = a2 >= 0.f ? a2 : 0.2f*a2;
        float a3 = red2(acc2[i][3]); a3 = a3 >= 0.f ? a3 : 0.2f*a3;
        int pix = b*HW + (by + py0 + 4*i)*WW + (bx + px);
        reinterpret_cast<float4*>(g_hm + pix*CMID)[og] = make_float4(a0, a1, a2, a3);
    }
}

// ---------------------------------------------------------------------------
// K3: conv2 + tanh offset + warp-per-pixel coalesced gather + coalesced store
// ---------------------------------------------------------------------------
__global__ __launch_bounds__(256, 2) void k_sample(const float* __restrict__ w2,
                                                   const float* __restrict__ b2,
                                                   float* __restrict__ out) {
    extern __shared__ float sm[];
    float* sres = sm;                    // 256*66 = 16896
    float* ht   = sm + 16896;            // 324*17 = 5508
    float* ws2  = sm + 22404;            // 288
    float* swx  = sm + 22692;            // 256
    float* swy  = sm + 22948;            // 256
    int*   sxy  = (int*)(sm + 23204);    // 256
    float* b2s  = sm + 23460;            // 2   -> 23462 floats = 93848 B

    int blk = blockIdx.x;
    int b   = blk >> 8;
    int tt  = blk & 255;
    int by  = (tt >> 4) * TS, bx = (tt & 15) * TS;
    int tid = threadIdx.x;
    const float* hb = g_hm + b*HW*CMID;

    for (int idx = tid; idx < N18*16; idx += 256) {
        int hp = idx >> 4, c = idx & 15;
        int hy = by + hp/H18 - 1, hx = bx + hp%H18 - 1;
        float v = 0.f;
        if ((unsigned)hy < HH && (unsigned)hx < WW)
            v = hb[(hy*WW + hx)*CMID + c];
        ht[hp*17 + c] = v;
    }
    for (int i = tid; i < 288; i += 256) {
        int tp = i >> 5, c = (i >> 1) & 15, o = i & 1;
        int r  = tp / 3, s5 = tp - r*3;
        ws2[i] = w2[((o*CMID + c)*3 + r)*3 + s5];
    }
    if (tid < 2) b2s[tid] = b2[tid];
    __syncthreads();

    // phase 1: conv2 + tanh -> sampling params
    {
        int ty = tid >> 4, tx = tid & 15;
        float a0 = b2s[0], a1 = b2s[1];
#pragma unroll
        for (int tp = 0; tp < 9; tp++) {
            int r = tp / 3, s5 = tp - r*3;
            const float* row = ht + ((ty + r)*H18 + (tx + s5))*17;
            const float* wr  = ws2 + tp*32;
#pragma unroll
            for (int c = 0; c < 16; c++) {
                float f = row[c];
                a0 += f * wr[c*2];
                a1 += f * wr[c*2 + 1];
            }
        }
        float offx = tanhf(a0) * 0.1f;
        float offy = tanhf(a1) * 0.1f;
        float ix = (float)(bx + tx) + offx * 127.5f;
        float iy = (float)(by + ty) + offy * 127.5f;
        ix = fminf(fmaxf(ix, 0.f), 255.f);
        iy = fminf(fmaxf(iy, 0.f), 255.f);
        float x0f = floorf(ix), y0f = floorf(iy);
        int x0 = (int)x0f, y0 = (int)y0f;
        sxy[tid] = x0 | (y0 << 16);
        swx[tid] = ix - x0f;
        swy[tid] = iy - y0f;
    }
    __syncthreads();

    // phase 2: warp-per-pixel gather, lane = channel pair (coalesced LDG.64)
    {
        int wrp = tid >> 5, ln = tid & 31;
        const float2* xb2 = reinterpret_cast<const float2*>(g_xT + b*HW*CCH);
#pragma unroll 2
        for (int pi = 0; pi < 32; pi++) {
            int p  = wrp*32 + pi;
            int pk = sxy[p];
            int x0 = pk & 0xffff, y0 = pk >> 16;
            int x1 = min(x0 + 1, WW - 1), y1 = min(y0 + 1, HH - 1);
            float wx = swx[p], wy = swy[p];
            float2 v00 = xb2[(y0*WW + x0)*32 + ln];
            float2 v01 = xb2[(y0*WW + x1)*32 + ln];
            float2 v10 = xb2[(y1*WW + x0)*32 + ln];
            float2 v11 = xb2[(y1*WW + x1)*32 + ln];
            float omx = 1.f - wx, omy = 1.f - wy;
            float2 rr;
            rr.x = omy*(omx*v00.x + wx*v01.x) + wy*(omx*v10.x + wx*v11.x);
            rr.y = omy*(omx*v00.y + wx*v01.y) + wy*(omx*v10.y + wx*v11.y);
            *reinterpret_cast<float2*>(sres + p*66 + 2*ln) = rr;
        }
    }
    __syncthreads();

    // phase 3: thread-per-pixel coalesced NCHW store
    {
        int ty = tid >> 4, tx = tid & 15;
        float* ob = out + b*CCH*HW + (by + ty)*WW + (bx + tx);
        const float* my = sres + tid*66;
#pragma unroll
        for (int c = 0; c < 64; c++) ob[c*HW] = my[c];
    }
}

// ---------------------------------------------------------------------------
extern "C" void kernel_launch(void* const* d_in, const int* in_sizes, int n_in,
                              void* d_out, int out_size) {
    const float* x  = (const float*)d_in[0];
    const float* w1 = (const float*)d_in[1];
    const float* b1 = (const float*)d_in[2];
    const float* w2 = (const float*)d_in[3];
    const float* b2 = (const float*)d_in[4];
    float* out = (float*)d_out;

    const int smem1 = 41512 * 4;   // 166,048 B
    const int smem3 = 23462 * 4;   //  93,848 B
    cudaFuncSetAttribute(k_conv1,  cudaFuncAttributeMaxDynamicSharedMemorySize, smem1);
    cudaFuncSetAttribute(k_sample, cudaFuncAttributeMaxDynamicSharedMemorySize, smem3);

    k_transpose<<<BATCH * (HW/64), 256>>>(x);
    k_conv1   <<<BATCH * 256, 256, smem1>>>(w1, b1);
    k_sample  <<<BATCH * 256, 256, smem3>>>(w2, b2, out);
    (void)in_sizes; (void)n_in; (void)out_size;
}